// round 1
// baseline (speedup 1.0000x reference)
#include <cuda_runtime.h>

// Problem constants (fixed by the dataset)
#define BHV     32        // B*H = 2*16
#define SV      8192
#define DV      128
#define LV      32
#define STRIDEV 16
#define NBV     511       // sliding windows
#define NOUTB   512       // nb + 1 (zero block prepended)

#define GWIN    4         // windows per CTA
#define NGROUPS 128       // ceil(511/4)
#define NTHREADS 256
#define KC      64        // weight K-chunk staged in smem
#define WPAD    132       // padded row length of Wsm[KC][WPAD] (16B-aligned, conflict-spread)

// smem (floats): buf0[128*128] + buf1[64*128] + Wsm[KC*WPAD]
#define BUF0_FLOATS (GWIN * LV * DV)          // 16384
#define BUF1_FLOATS (GWIN * (LV / 2) * DV)    // 8192
#define SMEM_FLOATS (BUF0_FLOATS + BUF1_FLOATS + KC * WPAD)

__device__ __forceinline__ float silu_f(float v) {
    // v * sigmoid(v); __expf/__fdividef are ~2ulp — far inside the 1e-3 budget
    return __fdividef(v, 1.0f + __expf(-v));
}

// One stage GEMM: C[j][n] = sum_k A[j][k] * W[n][k]
//   A[j][k] = bufIn[j*Kdim + k]   (smem; pair-concat is contiguous by construction)
//   W       = global [128][Kdim], staged into Wsm[kk][n] in KC chunks
// R = rows per thread (ceil(Mout/16)). 16x16 thread grid, 8 cols/thread.
// If outSm != nullptr: apply silu, store to smem. Else: raw store to outGm.
template <int R>
__device__ __forceinline__ void stage_gemm(
    const float* __restrict__ bufIn,
    const float* __restrict__ Wg,
    float* __restrict__ Wsm,
    int Kdim, int Mout,
    float* __restrict__ outSm,
    float* __restrict__ outGm,
    int tid)
{
    const int ty = tid >> 4;   // 0..15 -> output row group
    const int tx = tid & 15;   // 0..15 -> 8-col group

    float acc[R][8];
#pragma unroll
    for (int r = 0; r < R; r++)
#pragma unroll
        for (int c = 0; c < 8; c++) acc[r][c] = 0.0f;

    for (int k0 = 0; k0 < Kdim; k0 += KC) {
        // Pre-load sync: (a) previous chunk's readers are done with Wsm,
        // (b) previous stage's smem writes are visible before first compute.
        __syncthreads();
        // Stage W chunk transposed: Wsm[kk][n] = W[n][k0+kk]
        // (consecutive threads read consecutive kk within an n -> coalesced LDG)
#pragma unroll 4
        for (int i = tid; i < 128 * KC; i += NTHREADS) {
            int n  = i >> 6;          // / KC
            int kk = i & (KC - 1);
            Wsm[kk * WPAD + n] = Wg[n * Kdim + k0 + kk];
        }
        __syncthreads();

        // For R==1 stages with Mout < 16, whole warps skip (ty pairs stay
        // warp-uniform for even Mout; odd Mout just predicates one lane pair).
        if (R > 1 || ty < Mout) {
#pragma unroll 4
            for (int kk = 0; kk < KC; kk++) {
                const int kg = k0 + kk;
                float a[R];
#pragma unroll
                for (int r = 0; r < R; r++)
                    a[r] = bufIn[(ty + 16 * r) * Kdim + kg];
                const float4* wp =
                    reinterpret_cast<const float4*>(Wsm + kk * WPAD + tx * 8);
                const float4 wa = wp[0];
                const float4 wb = wp[1];
#pragma unroll
                for (int r = 0; r < R; r++) {
                    acc[r][0] += a[r] * wa.x;
                    acc[r][1] += a[r] * wa.y;
                    acc[r][2] += a[r] * wa.z;
                    acc[r][3] += a[r] * wa.w;
                    acc[r][4] += a[r] * wb.x;
                    acc[r][5] += a[r] * wb.y;
                    acc[r][6] += a[r] * wb.z;
                    acc[r][7] += a[r] * wb.w;
                }
            }
        }
    }

    // Write outputs (guarded; invalid-row accumulators are simply dropped).
    // Safe vs other threads still computing: they read bufIn, we write the
    // *other* ping-pong buffer / gmem.
#pragma unroll
    for (int r = 0; r < R; r++) {
        const int j = ty + 16 * r;
        if (j < Mout) {
            if (outSm != nullptr) {
#pragma unroll
                for (int c = 0; c < 8; c++)
                    outSm[j * DV + tx * 8 + c] = silu_f(acc[r][c]);
            } else {
#pragma unroll
                for (int c = 0; c < 8; c++)
                    outGm[j * DV + tx * 8 + c] = acc[r][c];
            }
        }
    }
}

__global__ void __launch_bounds__(NTHREADS, 1)
compressor_kernel(const float* __restrict__ kten,
                  const float* __restrict__ pe,
                  const float* __restrict__ w_down,
                  const float* __restrict__ w_stop,
                  float* __restrict__ out)
{
    extern __shared__ float smem[];
    float* buf0 = smem;
    float* buf1 = smem + BUF0_FLOATS;
    float* Wsm  = smem + BUF0_FLOATS + BUF1_FLOATS;

    const int tid = threadIdx.x;
    const int cta = blockIdx.x;
    const int g   = cta & (NGROUPS - 1);
    const int bh  = cta >> 7;                 // / NGROUPS
    const int w0  = g * GWIN;
    const int gcount = min(GWIN, NBV - w0);   // last group has 3 windows

    // The prepended zero block (out block 0 per (b,h)); d_out is poisoned.
    if (g == 0 && tid < DV) {
        out[(size_t)bh * NOUTB * DV + tid] = 0.0f;
    }

    // Load the group's windows: buf0[wi*32 + r][d] = k[bh, 16*(w0+wi)+r, d] + pe[r][d]
    const float* kb = kten + (size_t)bh * SV * DV;
    const int total = gcount * LV * DV;       // multiple of 1024
    for (int idx = tid * 4; idx < total; idx += NTHREADS * 4) {
        const int d  = idx & (DV - 1);
        const int rr = idx >> 7;              // wi*32 + r
        const int wi = rr >> 5;
        const int r  = rr & 31;
        const int srow = STRIDEV * (w0 + wi) + r;
        float4 kv = *reinterpret_cast<const float4*>(kb + (size_t)srow * DV + d);
        const float4 pv = *reinterpret_cast<const float4*>(pe + r * DV + d);
        kv.x += pv.x; kv.y += pv.y; kv.z += pv.z; kv.w += pv.w;
        *reinterpret_cast<float4*>(buf0 + idx) = kv;
    }
    // No explicit sync: stage_gemm's pre-load __syncthreads covers visibility.

    // 5 hierarchical stages, ping-ponging buf0 <-> buf1.
    float* bin  = buf0;
    float* bout = buf1;
    for (int s = 0; s < 5; s++) {
        const float* Wg = w_down + (size_t)s * 128 * 256;
        const int Ms = (gcount << 5) >> (s + 1);   // gcount*32 / 2^(s+1)
        const int R  = (Ms + 15) >> 4;
        switch (R) {
            case 4: stage_gemm<4>(bin, Wg, Wsm, 256, Ms, bout, nullptr, tid); break;
            case 3: stage_gemm<3>(bin, Wg, Wsm, 256, Ms, bout, nullptr, tid); break;
            case 2: stage_gemm<2>(bin, Wg, Wsm, 256, Ms, bout, nullptr, tid); break;
            default: stage_gemm<1>(bin, Wg, Wsm, 256, Ms, bout, nullptr, tid); break;
        }
        float* t = bin; bin = bout; bout = t;
    }

    // w_stop: M = gcount rows, K = 128, no silu, straight to gmem.
    // Row j of bin corresponds to window w0+j -> out block w0+j+1.
    float* og = out + ((size_t)bh * NOUTB + (w0 + 1)) * DV;
    stage_gemm<1>(bin, w_stop, Wsm, 128, gcount, nullptr, og, tid);
}

extern "C" void kernel_launch(void* const* d_in, const int* in_sizes, int n_in,
                              void* d_out, int out_size)
{
    const float* k      = (const float*)d_in[0];   // [2,16,8192,128] f32
    const float* pe     = (const float*)d_in[1];   // [32,128] f32
    const float* w_down = (const float*)d_in[2];   // [5,128,256] f32
    const float* w_stop = (const float*)d_in[3];   // [128,128] f32
    float* out = (float*)d_out;                    // [2,16,512,128] f32

    const int smem_bytes = SMEM_FLOATS * (int)sizeof(float);   // 132096
    cudaFuncSetAttribute(compressor_kernel,
                         cudaFuncAttributeMaxDynamicSharedMemorySize, smem_bytes);

    compressor_kernel<<<BHV * NGROUPS, NTHREADS, smem_bytes>>>(
        k, pe, w_down, w_stop, out);
}

// round 6
// speedup vs baseline: 6.4252x; 6.4252x over previous
#include <cuda_runtime.h>
#include <cuda_bf16.h>
#include <stdint.h>

// ---------------- problem constants ----------------
#define BHV     32
#define SV      8192
#define DV      128
#define NBV     511
#define NOUTB   512
#define GWIN    4          // windows per CTA
#define NGROUPS 128
#define NTH     256

// ---------------- prepped weight images ----------------
// 22 K-chunks of 64: chunks 0..19 = w_down stages 0..4 (4 chunks each, K=256),
// chunks 20..21 = w_stop (K=128). Per chunk: [split(hi,lo)][n=128][72 padded k] bf16.
#define CHUNK_EL   (2 * 128 * 72)          // 18432 elements
#define CHUNK_B    (CHUNK_EL * 2)          // 36864 bytes
__device__ __align__(16) __nv_bfloat16 g_W[22 * CHUNK_EL];

// ---------------- smem layout (byte offsets) ----------------
// A stride = 264 bf16 (= 256 + 8 pad) = 528 B  -> conflict-free fragment LDS
#define OFF_AH0  0u            // bufA hi: 64 rows * 528 = 33792
#define OFF_AL0  33792u
#define OFF_AH1  67584u        // bufB hi: 32 rows * 528 = 16896
#define OFF_AL1  84480u
#define OFF_W    101376u       // 2 x 36864 = 73728
#define SMEM_BYTES 175104

// ---------------- helpers ----------------
__device__ __forceinline__ uint32_t s2u(const void* p) {
    uint32_t a;
    asm("{ .reg .u64 t; cvta.to.shared.u64 t, %1; cvt.u32.u64 %0, t; }" : "=r"(a) : "l"(p));
    return a;
}
// VOLATILE: smem contents change between same-address reads (double-buffered W
// ring has period 2 in a fully-unrolled loop; non-volatile asm is CSE-eligible
// and round-4 showed the compiler indeed reused chunk-c loads for chunk c+2).
__device__ __forceinline__ uint32_t lds32(uint32_t a) {
    uint32_t v; asm volatile("ld.shared.b32 %0, [%1];" : "=r"(v) : "r"(a)); return v;
}
__device__ __forceinline__ void sts32(uint32_t a, uint32_t v) {
    asm volatile("st.shared.b32 [%0], %1;" :: "r"(a), "r"(v) : "memory");
}
__device__ __forceinline__ void sts64(uint32_t a, uint32_t v0, uint32_t v1) {
    asm volatile("st.shared.v2.b32 [%0], {%1, %2};" :: "r"(a), "r"(v0), "r"(v1) : "memory");
}
__device__ __forceinline__ void sts128z(uint32_t a) {
    asm volatile("st.shared.v4.b32 [%0], {%1, %1, %1, %1};" :: "r"(a), "r"(0u) : "memory");
}
// pack two f32 -> bf16x2 (first arg lands in the LOW half = first element in mem)
__device__ __forceinline__ uint32_t packbf(float lo_el, float hi_el) {
    uint32_t r;
    asm("cvt.rn.bf16x2.f32 %0, %1, %2;" : "=r"(r) : "f"(hi_el), "f"(lo_el));
    return r;
}
__device__ __forceinline__ float silu_f(float v) {
    return __fdividef(v, 1.0f + __expf(-v));
}
__device__ __forceinline__ void hmma(float acc[4],
                                     uint32_t a0, uint32_t a1, uint32_t a2, uint32_t a3,
                                     uint32_t b0, uint32_t b1) {
    asm("mma.sync.aligned.m16n8k16.row.col.f32.bf16.bf16.f32 "
        "{%0,%1,%2,%3}, {%4,%5,%6,%7}, {%8,%9}, {%0,%1,%2,%3};"
        : "+f"(acc[0]), "+f"(acc[1]), "+f"(acc[2]), "+f"(acc[3])
        : "r"(a0), "r"(a1), "r"(a2), "r"(a3), "r"(b0), "r"(b1));
}
// copy one 36864 B chunk: 2304 x 16B, 9 per thread
__device__ __forceinline__ void copy_chunk(uint32_t dst, const char* src, int tid) {
#pragma unroll
    for (int i = 0; i < 9; i++) {
        const int o = (tid + i * NTH) * 16;
        asm volatile("cp.async.cg.shared.global [%0], [%1], 16;"
                     :: "r"(dst + o), "l"(src + o) : "memory");
    }
}
#define CP_COMMIT() asm volatile("cp.async.commit_group;" ::: "memory")
#define CP_WAIT1()  asm volatile("cp.async.wait_group 1;" ::: "memory")
#define CP_WAIT0()  asm volatile("cp.async.wait_group 0;" ::: "memory")

// ---------------- weight prep (runs every launch; ~5 µs) ----------------
__global__ void prep_weights(const float* __restrict__ wd, const float* __restrict__ ws) {
    const int idx = blockIdx.x * blockDim.x + threadIdx.x;  // 22*8192
    if (idx >= 22 * 8192) return;
    const int gc = idx >> 13, rem = idx & 8191;
    const int n = rem >> 6, kk = rem & 63;
    const int st = (gc < 20) ? (gc >> 2) : 5;
    const int ch = (gc < 20) ? (gc & 3) : (gc - 20);
    const int k = ch * 64 + kk;
    const float v = (st < 5) ? wd[st * 32768 + n * 256 + k] : ws[n * 128 + k];
    const __nv_bfloat16 h = __float2bfloat16(v);
    const float l = v - __bfloat162float(h);
    const size_t base = (size_t)gc * CHUNK_EL;
    g_W[base + n * 72 + kk] = h;                           // hi split
    g_W[base + 9216 + n * 72 + kk] = __float2bfloat16(l);  // lo split
}

// ---------------- one stage: NC K-chunks of 64, then epilogue ----------------
// MODE 0: silu + pair-concat restage; MODE 1: silu + direct restage (pre-w_stop);
// MODE 2: raw f32 to gmem.
template <int NT, int NC, int MODE>
__device__ __forceinline__ void stage_run(
    uint32_t aHr, uint32_t aLr, uint32_t aHw, uint32_t aLw,
    uint32_t wsm, const char* gw, int gcbase, int& gcnext,
    int tid, int mv, float* gout)
{
    const int lane = tid & 31, wid = tid >> 5;
    constexpr int WPM = 16 / NT;                 // warps per m-tile
    const int mt = wid / WPM;
    const int nbase = (wid % WPM) * (NT * 8);

    float acc[NT][4];
#pragma unroll
    for (int i = 0; i < NT; i++)
        acc[i][0] = acc[i][1] = acc[i][2] = acc[i][3] = 0.0f;

#pragma unroll
    for (int c = 0; c < NC; c++) {
        const int gcur = gcbase + c;
        if (gcnext < 22) {
            copy_chunk(wsm + (uint32_t)((gcnext & 1) * CHUNK_B),
                       gw + (size_t)gcnext * CHUNK_B, tid);
            CP_COMMIT();
            gcnext++;
        }
        if (gcur < 21) CP_WAIT1(); else CP_WAIT0();
        __syncthreads();

        const uint32_t wb  = wsm + (uint32_t)((gcur & 1) * CHUNK_B);
        const uint32_t wbl = wb + 18432;         // lo split image
        const int kofs = c * 128;                // bytes into the A row

#pragma unroll
        for (int ks = 0; ks < 4; ks++) {
            const uint32_t ar = aHr +
                (uint32_t)((mt * 16 + (lane >> 2)) * 528 + kofs + ks * 32 + (lane & 3) * 4);
            const uint32_t al = ar + (aLr - aHr);
            const uint32_t ah0 = lds32(ar),            ah1 = lds32(ar + 8 * 528);
            const uint32_t ah2 = lds32(ar + 16),       ah3 = lds32(ar + 8 * 528 + 16);
            const uint32_t al0 = lds32(al),            al1 = lds32(al + 8 * 528);
            const uint32_t al2 = lds32(al + 16),       al3 = lds32(al + 8 * 528 + 16);
#pragma unroll
            for (int nt = 0; nt < NT; nt++) {
                const uint32_t wo = (uint32_t)((nbase + nt * 8 + (lane >> 2)) * 144
                                               + ks * 32 + (lane & 3) * 4);
                const uint32_t bh0 = lds32(wb + wo),  bh1 = lds32(wb + wo + 16);
                const uint32_t bl0 = lds32(wbl + wo), bl1 = lds32(wbl + wo + 16);
                hmma(acc[nt], ah0, ah1, ah2, ah3, bh0, bh1);
                hmma(acc[nt], ah0, ah1, ah2, ah3, bl0, bl1);
                hmma(acc[nt], al0, al1, al2, al3, bh0, bh1);
            }
        }
        __syncthreads();
    }

    // epilogue
#pragma unroll
    for (int nt = 0; nt < NT; nt++) {
        const int c0 = nbase + nt * 8 + ((lane & 3) << 1);
        const int r0 = mt * 16 + (lane >> 2);
#pragma unroll
        for (int h = 0; h < 2; h++) {
            const int r = r0 + h * 8;
            const float va = acc[nt][2 * h], vb = acc[nt][2 * h + 1];
            if (r < mv) {
                if (MODE == 2) {
                    *reinterpret_cast<float2*>(gout + r * 128 + c0) = make_float2(va, vb);
                } else {
                    const float sa = silu_f(va), sb = silu_f(vb);
                    const float hA = __bfloat162float(__float2bfloat16(sa));
                    const float hB = __bfloat162float(__float2bfloat16(sb));
                    const uint32_t doff = (MODE == 0)
                        ? (uint32_t)(((r >> 1) * 528) + (((((r & 1) << 7) + c0)) << 1))
                        : (uint32_t)((r * 528) + (c0 << 1));
                    sts32(aHw + doff, packbf(hA, hB));
                    sts32(aLw + doff, packbf(sa - hA, sb - hB));
                }
            }
        }
    }
}

// ---------------- main fused kernel ----------------
__global__ void __launch_bounds__(NTH, 1)
comp_main(const float* __restrict__ kten, const float* __restrict__ pe,
          float* __restrict__ out)
{
    extern __shared__ __align__(16) char smem[];
    const uint32_t sb = s2u(smem);
    const uint32_t AH0 = sb + OFF_AH0, AL0 = sb + OFF_AL0;
    const uint32_t AH1 = sb + OFF_AH1, AL1 = sb + OFF_AL1;
    const uint32_t WS  = sb + OFF_W;

    const int tid = threadIdx.x;
    const int g  = blockIdx.x & (NGROUPS - 1);
    const int bh = blockIdx.x >> 7;
    const int w0 = g * GWIN;
    const int gcount = min(GWIN, NBV - w0);
    const char* gw = (const char*)g_W;

    // prefetch weight chunk 0 immediately (overlaps input load)
    copy_chunk(WS, gw, tid);
    CP_COMMIT();
    int gcnext = 1;

    // the prepended zero block
    if (g == 0 && tid < DV)
        out[(size_t)bh * NOUTB * DV + tid] = 0.0f;

    // partial last group: zero A buffers so garbage rows stay finite
    if (gcount < GWIN) {
        for (uint32_t i = (uint32_t)tid * 16; i < OFF_W; i += NTH * 16)
            sts128z(sb + i);
        __syncthreads();
    }

    // input: gcount*32 rows of k (+pe), split hi/lo, store as A0 [64 x 256]
    const float* kb = kten + (size_t)bh * SV * DV;
#pragma unroll
    for (int it = 0; it < 16; ++it) {
        const int idx = tid + it * NTH;          // float4 index, 0..4095
        const int r_in = idx >> 5, d4 = idx & 31;
        const int wi = r_in >> 5, rr = r_in & 31;
        if (wi < gcount) {
            const int grow = 16 * (w0 + wi) + rr;
            const float4 kv = *reinterpret_cast<const float4*>(kb + (size_t)grow * DV + d4 * 4);
            const float4 pv = *reinterpret_cast<const float4*>(pe + rr * DV + d4 * 4);
            const float v0 = kv.x + pv.x, v1 = kv.y + pv.y;
            const float v2 = kv.z + pv.z, v3 = kv.w + pv.w;
            const float h0 = __bfloat162float(__float2bfloat16(v0));
            const float h1 = __bfloat162float(__float2bfloat16(v1));
            const float h2 = __bfloat162float(__float2bfloat16(v2));
            const float h3 = __bfloat162float(__float2bfloat16(v3));
            const uint32_t doff =
                (uint32_t)(((r_in >> 1) * 528) + ((((r_in & 1) << 7) + d4 * 4) << 1));
            sts64(AH0 + doff, packbf(h0, h1), packbf(h2, h3));
            sts64(AL0 + doff, packbf(v0 - h0, v1 - h1), packbf(v2 - h2, v3 - h3));
        }
    }
    // (stage_run's first wait+__syncthreads orders these STS before any LDS)

    float* gout = out + ((size_t)bh * NOUTB + w0 + 1) * DV;

    stage_run<8, 4, 0>(AH0, AL0, AH1, AL1, WS, gw,  0, gcnext, tid, gcount * 16, nullptr);
    stage_run<4, 4, 0>(AH1, AL1, AH0, AL0, WS, gw,  4, gcnext, tid, gcount *  8, nullptr);
    stage_run<2, 4, 0>(AH0, AL0, AH1, AL1, WS, gw,  8, gcnext, tid, gcount *  4, nullptr);
    stage_run<2, 4, 0>(AH1, AL1, AH0, AL0, WS, gw, 12, gcnext, tid, gcount *  2, nullptr);
    stage_run<2, 4, 1>(AH0, AL0, AH1, AL1, WS, gw, 16, gcnext, tid, gcount,      nullptr);
    stage_run<2, 2, 2>(AH1, AL1, 0, 0,     WS, gw, 20, gcnext, tid, gcount,      gout);
}

// ---------------- launch ----------------
extern "C" void kernel_launch(void* const* d_in, const int* in_sizes, int n_in,
                              void* d_out, int out_size)
{
    const float* k      = (const float*)d_in[0];   // [2,16,8192,128] f32
    const float* pe     = (const float*)d_in[1];   // [32,128] f32
    const float* w_down = (const float*)d_in[2];   // [5,128,256] f32
    const float* w_stop = (const float*)d_in[3];   // [128,128] f32
    float* out = (float*)d_out;                    // [2,16,512,128] f32

    prep_weights<<<(22 * 8192 + 255) / 256, 256>>>(w_down, w_stop);

    cudaFuncSetAttribute(comp_main,
                         cudaFuncAttributeMaxDynamicSharedMemorySize, SMEM_BYTES);
    comp_main<<<BHV * NGROUPS, NTH, SMEM_BYTES>>>(k, pe, out);
}